// round 11
// baseline (speedup 1.0000x reference)
#include <cuda_runtime.h>
#include <cuda_bf16.h>
#include <cuda_fp16.h>
#include <cstdint>

// ---------------- problem constants ----------------
#define BB   8
#define NT   2
#define NN   2000
#define ENN  4000
#define NNZE 32000
#define LL   8
#define DD   64
#define LD   512
#define SEG  (BB*NT)
#define NPB  8             // nodes per block -> M = 64
#define NBLK (NN/NPB)      // 250
#define KD   192
#define BCAP 64            // bucket capacity; Poisson(16) => P(>64) ~ 1e-20

// A smem: 64 rows x 200 bf16 slots (400 B/row, 192 used). hi then lo.
#define AROW 200
#define A_BYTES (64 * AROW * 2)      // 25600
#define SMEM_TOTAL (2 * A_BYTES)

#define STATE_ELEMS ((size_t)BB * ENN * LD)    // 16,384,000 per tensor
#define CONV_PER (int)(STATE_ELEMS / 8)        // 2,048,000 threads per tensor

// ---------------- device scratch ----------------
__device__ int   g_cnt [SEG * NN];
__device__ int2  g_bkt [(size_t)SEG * NN * BCAP];   // packed {val bits, col}
__device__ __align__(16) __half g_s16[2 * STATE_ELEMS];   // fp16 state_in | state_out
// W images: [mat(3)][n(64)][k(192)] bf16, hi and lo
__device__ __align__(16) __nv_bfloat16 g_Wb_hi[3 * 64 * 192];
__device__ __align__(16) __nv_bfloat16 g_Wb_lo[3 * 64 * 192];

// ---------------- helpers ----------------
__device__ __forceinline__ uint32_t smem_u32(const void* p) {
    uint32_t a;
    asm("{ .reg .u64 t; cvta.to.shared.u64 t, %1; cvt.u32.u64 %0, t; }" : "=r"(a) : "l"(p));
    return a;
}
__device__ __forceinline__ float sigm(float x) { return 1.0f / (1.0f + __expf(-x)); }

#define LDMATRIX_X4(r0, r1, r2, r3, addr) \
    asm volatile("ldmatrix.sync.aligned.m8n8.x4.shared.b16 {%0,%1,%2,%3}, [%4];" \
        : "=r"(r0), "=r"(r1), "=r"(r2), "=r"(r3) : "r"(addr))

#define MMA16816(c, a0, a1, a2, a3, b0, b1) \
    asm volatile("mma.sync.aligned.m16n8k16.row.col.f32.bf16.bf16.f32 " \
        "{%0,%1,%2,%3}, {%4,%5,%6,%7}, {%8,%9}, {%0,%1,%2,%3};" \
        : "+f"((c)[0]), "+f"((c)[1]), "+f"((c)[2]), "+f"((c)[3]) \
        : "r"(a0), "r"(a1), "r"(a2), "r"(a3), "r"(b0), "r"(b1))

// fp16-row FMA: 8 halves (one uint4) scaled into 8 fp32 accumulators
__device__ __forceinline__ void fma8(float* a, const uint4& p, float v) {
    const __half2* h = reinterpret_cast<const __half2*>(&p);
#pragma unroll
    for (int q = 0; q < 4; ++q) {
        float2 f = __half22float2(h[q]);
        a[2 * q]     += v * f.x;
        a[2 * q + 1] += v * f.y;
    }
}

// pack 8 fp32 -> bf16 hi uint4 + lo uint4
__device__ __forceinline__ void pack_hilo(const float* a, uint4& hw, uint4& lw) {
    uint32_t* hp = reinterpret_cast<uint32_t*>(&hw);
    uint32_t* lp = reinterpret_cast<uint32_t*>(&lw);
#pragma unroll
    for (int q = 0; q < 4; ++q) {
        __nv_bfloat162 h2 = __floats2bfloat162_rn(a[2 * q], a[2 * q + 1]);
        __nv_bfloat162 l2 = __floats2bfloat162_rn(a[2 * q]     - __bfloat162float(h2.x),
                                                  a[2 * q + 1] - __bfloat162float(h2.y));
        hp[q] = *reinterpret_cast<uint32_t*>(&h2);
        lp[q] = *reinterpret_cast<uint32_t*>(&l2);
    }
}

// ---------------- init: fp16 state conversion + zero counts + W prep ----------------
__global__ void k_init(const float* __restrict__ state_in,
                       const float* __restrict__ state_out,
                       const float* __restrict__ Wr,
                       const float* __restrict__ Wz,
                       const float* __restrict__ Wh) {
    int idx = blockIdx.x * blockDim.x + threadIdx.x;
    if (idx < 2 * CONV_PER) {
        const bool second = (idx >= CONV_PER);
        const float* src = second ? state_out : state_in;
        const size_t base = (size_t)(second ? idx - CONV_PER : idx) * 8;
        __half* dst = g_s16 + (second ? STATE_ELEMS : 0) + base;
        float4 x0 = __ldg(reinterpret_cast<const float4*>(src + base));
        float4 x1 = __ldg(reinterpret_cast<const float4*>(src + base) + 1);
        uint4 o;
        __half2 h;
        h = __floats2half2_rn(x0.x, x0.y); o.x = *reinterpret_cast<uint32_t*>(&h);
        h = __floats2half2_rn(x0.z, x0.w); o.y = *reinterpret_cast<uint32_t*>(&h);
        h = __floats2half2_rn(x1.x, x1.y); o.z = *reinterpret_cast<uint32_t*>(&h);
        h = __floats2half2_rn(x1.z, x1.w); o.w = *reinterpret_cast<uint32_t*>(&h);
        *reinterpret_cast<uint4*>(dst) = o;
    }
    if (idx < SEG * NN) g_cnt[idx] = 0;
    if (idx < 3 * 64 * 192) {
        int mat = idx / (64 * 192);
        int r   = idx - mat * (64 * 192);
        const float* W = (mat == 0) ? Wr : (mat == 1) ? Wz : Wh;
        float w = W[r];
        __nv_bfloat16 hi = __float2bfloat16(w);
        __nv_bfloat16 lo = __float2bfloat16(w - __bfloat162float(hi));
        g_Wb_hi[idx] = hi;
        g_Wb_lo[idx] = lo;
    }
}

// ---------------- single-pass bucketed edge build ----------------
__global__ void k_scatter(const float* __restrict__ vals,
                          const int*   __restrict__ rows,
                          const int*   __restrict__ cols) {
    int idx = blockIdx.x * blockDim.x + threadIdx.x;
    if (idx >= SEG * NNZE) return;
    int seg = idx / NNZE;
    int slot = seg * NN + rows[idx];
    int pos = atomicAdd(&g_cnt[slot], 1);
    if (pos < BCAP)
        g_bkt[(size_t)slot * BCAP + pos] = make_int2(__float_as_int(vals[idx]), cols[idx]);
}

// ---------------- main fused kernel ----------------
__global__ void __launch_bounds__(256)
k_main(const float* __restrict__ state_cur,
       const float* __restrict__ b_r,
       const float* __restrict__ b_z,
       const float* __restrict__ b_h,
       float* __restrict__ out) {
    extern __shared__ char smem[];
    __nv_bfloat16* Ah = reinterpret_cast<__nv_bfloat16*>(smem);
    __nv_bfloat16* Al = reinterpret_cast<__nv_bfloat16*>(smem + A_BYTES);
    const uint32_t sbh = smem_u32(smem);
    const uint32_t sbl = sbh + A_BYTES;

    const int tid  = threadIdx.x;
    const int w    = tid >> 5;
    const int lane = tid & 31;
    const int b    = blockIdx.x / NBLK;
    const int nb   = (blockIdx.x - b * NBLK) * NPB;

    // ---------- Phase 1: SpMM gather over fp16 state (half the bytes) ----------
    for (int task = w; task < 16; task += 8) {
        const int node = task >> 1;
        const int type = task & 1;
        const int n    = nb + node;
        const int seg  = b * NT + type;
        const int slot = seg * NN + n;
        const __half* S = g_s16 + (type ? STATE_ELEMS : 0) + (size_t)b * ENN * LD;
        const int2*  E  = g_bkt + (size_t)slot * BCAP;
        int rem = g_cnt[slot];
        if (rem > BCAP) rem = BCAP;

        float acc0[8], acc1[8];
#pragma unroll
        for (int q = 0; q < 8; ++q) { acc0[q] = 0.0f; acc1[q] = 0.0f; }

        if (rem > 0) {
            int2 e0 = __ldg(&E[0]);
            int2 e1 = __ldg(&E[(rem > 1) ? 1 : 0]);
            const uint4* r0p = reinterpret_cast<const uint4*>(S + (size_t)e0.y * LD);
            const uint4* r1p = reinterpret_cast<const uint4*>(S + (size_t)e1.y * LD);
            uint4 pa0 = __ldg(r0p + lane);
            uint4 pa1 = __ldg(r0p + 32 + lane);
            uint4 pb0 = __ldg(r1p + lane);
            uint4 pb1 = __ldg(r1p + 32 + lane);

            int i = 0;
            while (i + 2 <= rem) {
                const int i2 = (i + 2 < rem) ? (i + 2) : (rem - 1);
                const int i3 = (i + 3 < rem) ? (i + 3) : (rem - 1);
                int2 f0 = __ldg(&E[i2]);
                int2 f1 = __ldg(&E[i3]);

                const float va = __int_as_float(e0.x);
                const float vb = __int_as_float(e1.x);

                fma8(acc0, pa0, va);
                fma8(acc1, pa1, va);
                fma8(acc0, pb0, vb);
                fma8(acc1, pb1, vb);

                const uint4* q0p = reinterpret_cast<const uint4*>(S + (size_t)f0.y * LD);
                const uint4* q1p = reinterpret_cast<const uint4*>(S + (size_t)f1.y * LD);
                pa0 = __ldg(q0p + lane);
                pa1 = __ldg(q0p + 32 + lane);
                pb0 = __ldg(q1p + lane);
                pb1 = __ldg(q1p + 32 + lane);

                e0 = f0; e1 = f1;
                i += 2;
            }
            if (i < rem) {
                const float va = __int_as_float(e0.x);
                fma8(acc0, pa0, va);
                fma8(acc1, pa1, va);
            }
        }

        // acc0 -> row halves [lane*8, +8): l = lane>>3 ; acc1 -> +256: l = 4 + (lane>>3)
        const int l0 = lane >> 3;
        const int d0 = (lane & 7) * 8;
        const int kb = type * DD + d0;
        uint4 hw, lw;
        pack_hilo(acc0, hw, lw);
        {
            const int row = node * LL + l0;
            *reinterpret_cast<uint4*>(&Ah[row * AROW + kb]) = hw;
            *reinterpret_cast<uint4*>(&Al[row * AROW + kb]) = lw;
        }
        pack_hilo(acc1, hw, lw);
        {
            const int row = node * LL + 4 + l0;
            *reinterpret_cast<uint4*>(&Ah[row * AROW + kb]) = hw;
            *reinterpret_cast<uint4*>(&Al[row * AROW + kb]) = lw;
        }
    }
    // state_cur (fp32): warp w loads node w
    {
        const int n = nb + w;
        const float4* C = reinterpret_cast<const float4*>(state_cur + (size_t)(b * NN + n) * LD);
#pragma unroll
        for (int j = 0; j < 4; ++j) {
            const int Eidx = j * 32 + lane;
            const int l    = Eidx >> 4;
            const int d4   = (Eidx & 15) * 4;
            float4 vx = __ldg(C + Eidx);
            const int row = w * LL + l;
            const int kb  = 128 + d4;
            __nv_bfloat162 h01 = __floats2bfloat162_rn(vx.x, vx.y);
            __nv_bfloat162 h23 = __floats2bfloat162_rn(vx.z, vx.w);
            __nv_bfloat162 l01 = __floats2bfloat162_rn(vx.x - __bfloat162float(h01.x),
                                                       vx.y - __bfloat162float(h01.y));
            __nv_bfloat162 l23 = __floats2bfloat162_rn(vx.z - __bfloat162float(h23.x),
                                                       vx.w - __bfloat162float(h23.y));
            uint2 hw, lw;
            hw.x = *reinterpret_cast<uint32_t*>(&h01);
            hw.y = *reinterpret_cast<uint32_t*>(&h23);
            lw.x = *reinterpret_cast<uint32_t*>(&l01);
            lw.y = *reinterpret_cast<uint32_t*>(&l23);
            *reinterpret_cast<uint2*>(&Ah[row * AROW + kb]) = hw;
            *reinterpret_cast<uint2*>(&Al[row * AROW + kb]) = lw;
        }
    }
    __syncthreads();

    // ---------- Phase 2: HMMA GEMMs ----------
    const int n0 = w * 8;
    const int qr = lane >> 2;
    const int qc = (lane & 3) * 2;

    float cr[16], cz[16], ch[16];
#pragma unroll
    for (int i = 0; i < 16; ++i) { cr[i] = 0.0f; cz[i] = 0.0f; ch[i] = 0.0f; }

    const int arow = lane & 15;
    const int koff16 = ((lane >> 4) & 1) * 16;
    const int bnr = (n0 + qr) * 192 + qc;

#pragma unroll
    for (int kt = 0; kt < 8; ++kt) {
        const int k0 = kt * 16;
        const uint32_t brh0 = *reinterpret_cast<const uint32_t*>(g_Wb_hi + bnr + k0);
        const uint32_t brh1 = *reinterpret_cast<const uint32_t*>(g_Wb_hi + bnr + k0 + 8);
        const uint32_t brl0 = *reinterpret_cast<const uint32_t*>(g_Wb_lo + bnr + k0);
        const uint32_t brl1 = *reinterpret_cast<const uint32_t*>(g_Wb_lo + bnr + k0 + 8);
        const uint32_t bzh0 = *reinterpret_cast<const uint32_t*>(g_Wb_hi + 64*192 + bnr + k0);
        const uint32_t bzh1 = *reinterpret_cast<const uint32_t*>(g_Wb_hi + 64*192 + bnr + k0 + 8);
        const uint32_t bzl0 = *reinterpret_cast<const uint32_t*>(g_Wb_lo + 64*192 + bnr + k0);
        const uint32_t bzl1 = *reinterpret_cast<const uint32_t*>(g_Wb_lo + 64*192 + bnr + k0 + 8);
        const uint32_t bhh0 = *reinterpret_cast<const uint32_t*>(g_Wb_hi + 128*192 + bnr + k0);
        const uint32_t bhh1 = *reinterpret_cast<const uint32_t*>(g_Wb_hi + 128*192 + bnr + k0 + 8);
        const uint32_t bhl0 = *reinterpret_cast<const uint32_t*>(g_Wb_lo + 128*192 + bnr + k0);
        const uint32_t bhl1 = *reinterpret_cast<const uint32_t*>(g_Wb_lo + 128*192 + bnr + k0 + 8);
#pragma unroll
        for (int i = 0; i < 4; ++i) {
            const uint32_t aoff = (uint32_t)((16 * i + arow) * 400 + k0 * 2 + koff16);
            uint32_t ah0, ah1, ah2, ah3, al0, al1, al2, al3;
            LDMATRIX_X4(ah0, ah1, ah2, ah3, sbh + aoff);
            LDMATRIX_X4(al0, al1, al2, al3, sbl + aoff);
            MMA16816(cr + 4*i, ah0, ah1, ah2, ah3, brh0, brh1);
            MMA16816(cr + 4*i, al0, al1, al2, al3, brh0, brh1);
            MMA16816(cr + 4*i, ah0, ah1, ah2, ah3, brl0, brl1);
            MMA16816(cz + 4*i, ah0, ah1, ah2, ah3, bzh0, bzh1);
            MMA16816(cz + 4*i, al0, al1, al2, al3, bzh0, bzh1);
            MMA16816(cz + 4*i, ah0, ah1, ah2, ah3, bzl0, bzl1);
            MMA16816(ch + 4*i, ah0, ah1, ah2, ah3, bhh0, bhh1);
            MMA16816(ch + 4*i, al0, al1, al2, al3, bhh0, bhh1);
            MMA16816(ch + 4*i, ah0, ah1, ah2, ah3, bhl0, bhl1);
        }
    }
#pragma unroll
    for (int kt = 8; kt < 12; ++kt) {
        const int k0 = kt * 16;
        const uint32_t brh0 = *reinterpret_cast<const uint32_t*>(g_Wb_hi + bnr + k0);
        const uint32_t brh1 = *reinterpret_cast<const uint32_t*>(g_Wb_hi + bnr + k0 + 8);
        const uint32_t brl0 = *reinterpret_cast<const uint32_t*>(g_Wb_lo + bnr + k0);
        const uint32_t brl1 = *reinterpret_cast<const uint32_t*>(g_Wb_lo + bnr + k0 + 8);
        const uint32_t bzh0 = *reinterpret_cast<const uint32_t*>(g_Wb_hi + 64*192 + bnr + k0);
        const uint32_t bzh1 = *reinterpret_cast<const uint32_t*>(g_Wb_hi + 64*192 + bnr + k0 + 8);
        const uint32_t bzl0 = *reinterpret_cast<const uint32_t*>(g_Wb_lo + 64*192 + bnr + k0);
        const uint32_t bzl1 = *reinterpret_cast<const uint32_t*>(g_Wb_lo + 64*192 + bnr + k0 + 8);
#pragma unroll
        for (int i = 0; i < 4; ++i) {
            const uint32_t aoff = (uint32_t)((16 * i + arow) * 400 + k0 * 2 + koff16);
            uint32_t ah0, ah1, ah2, ah3, al0, al1, al2, al3;
            LDMATRIX_X4(ah0, ah1, ah2, ah3, sbh + aoff);
            LDMATRIX_X4(al0, al1, al2, al3, sbl + aoff);
            MMA16816(cr + 4*i, ah0, ah1, ah2, ah3, brh0, brh1);
            MMA16816(cr + 4*i, al0, al1, al2, al3, brh0, brh1);
            MMA16816(cr + 4*i, ah0, ah1, ah2, ah3, brl0, brl1);
            MMA16816(cz + 4*i, ah0, ah1, ah2, ah3, bzh0, bzh1);
            MMA16816(cz + 4*i, al0, al1, al2, al3, bzh0, bzh1);
            MMA16816(cz + 4*i, ah0, ah1, ah2, ah3, bzl0, bzl1);
        }
    }
    __syncthreads();

    // ---------- Epilogue 1: r, z; write rc = r*cur over cur columns ----------
    float curv[16], zreg[16];
#pragma unroll
    for (int i = 0; i < 4; ++i) {
#pragma unroll
        for (int rr = 0; rr < 2; ++rr) {
            const int m = 16 * i + qr + 8 * rr;
#pragma unroll
            for (int cc = 0; cc < 2; ++cc) {
                const int o   = n0 + qc + cc;
                const int idx = i * 4 + rr * 2 + cc;
                const int e   = m * AROW + 128 + o;
                const float cur = __bfloat162float(Ah[e]) + __bfloat162float(Al[e]);
                curv[idx] = cur;
                const float rv = sigm(cr[idx] + __ldg(&b_r[o]));
                zreg[idx] = sigm(cz[idx] + __ldg(&b_z[o]));
                const float rc = rv * cur;
                const __nv_bfloat16 hi = __float2bfloat16(rc);
                Ah[e] = hi;
                Al[e] = __float2bfloat16(rc - __bfloat162float(hi));
            }
        }
    }
    __syncthreads();

    // ---------- Phase 3: finish h with rc columns ----------
#pragma unroll
    for (int kt = 8; kt < 12; ++kt) {
        const int k0 = kt * 16;
        const uint32_t bhh0 = *reinterpret_cast<const uint32_t*>(g_Wb_hi + 128*192 + bnr + k0);
        const uint32_t bhh1 = *reinterpret_cast<const uint32_t*>(g_Wb_hi + 128*192 + bnr + k0 + 8);
        const uint32_t bhl0 = *reinterpret_cast<const uint32_t*>(g_Wb_lo + 128*192 + bnr + k0);
        const uint32_t bhl1 = *reinterpret_cast<const uint32_t*>(g_Wb_lo + 128*192 + bnr + k0 + 8);
#pragma unroll
        for (int i = 0; i < 4; ++i) {
            const uint32_t aoff = (uint32_t)((16 * i + arow) * 400 + k0 * 2 + koff16);
            uint32_t ah0, ah1, ah2, ah3, al0, al1, al2, al3;
            LDMATRIX_X4(ah0, ah1, ah2, ah3, sbh + aoff);
            LDMATRIX_X4(al0, al1, al2, al3, sbl + aoff);
            MMA16816(ch + 4*i, ah0, ah1, ah2, ah3, bhh0, bhh1);
            MMA16816(ch + 4*i, al0, al1, al2, al3, bhh0, bhh1);
            MMA16816(ch + 4*i, ah0, ah1, ah2, ah3, bhl0, bhl1);
        }
    }

    // ---------- Epilogue 2: GRU combine + store ----------
#pragma unroll
    for (int i = 0; i < 4; ++i) {
#pragma unroll
        for (int rr = 0; rr < 2; ++rr) {
            const int m    = 16 * i + qr + 8 * rr;
            const int node = m >> 3;
            const int l    = m & 7;
            const size_t grow = ((size_t)(b * NN + nb + node) * LL + l);
            float2 v;
#pragma unroll
            for (int cc = 0; cc < 2; ++cc) {
                const int o   = n0 + qc + cc;
                const int idx = i * 4 + rr * 2 + cc;
                const float h = tanhf(ch[idx] + __ldg(&b_h[o]));
                const float z = zreg[idx];
                const float r2 = (1.0f - z) * curv[idx] + z * h;
                if (cc == 0) v.x = r2; else v.y = r2;
            }
            *reinterpret_cast<float2*>(out + grow * DD + n0 + qc) = v;
        }
    }
}

// ---------------- launch ----------------
extern "C" void kernel_launch(void* const* d_in, const int* in_sizes, int n_in,
                              void* d_out, int out_size) {
    (void)in_sizes; (void)n_in; (void)out_size;
    const float* state_in  = (const float*)d_in[0];
    const float* state_out = (const float*)d_in[1];
    const float* state_cur = (const float*)d_in[2];
    const float* A_vals    = (const float*)d_in[3];
    const int*   A_rows    = (const int*)  d_in[4];
    const int*   A_cols    = (const int*)  d_in[5];
    const float* W_r       = (const float*)d_in[6];
    const float* b_r       = (const float*)d_in[7];
    const float* W_z       = (const float*)d_in[8];
    const float* b_z       = (const float*)d_in[9];
    const float* W_h       = (const float*)d_in[10];
    const float* b_h       = (const float*)d_in[11];
    float* out = (float*)d_out;

    cudaFuncSetAttribute(k_main, cudaFuncAttributeMaxDynamicSharedMemorySize, SMEM_TOTAL);

    k_init<<<(2 * CONV_PER + 255) / 256, 256>>>(state_in, state_out, W_r, W_z, W_h);
    k_scatter<<<(SEG * NNZE + 255) / 256, 256>>>(A_vals, A_rows, A_cols);
    k_main<<<BB * NBLK, 256, SMEM_TOTAL>>>(state_cur, b_r, b_z, b_h, out);
}

// round 12
// speedup vs baseline: 1.0270x; 1.0270x over previous
#include <cuda_runtime.h>
#include <cuda_bf16.h>
#include <cuda_fp16.h>
#include <cstdint>

// ---------------- problem constants ----------------
#define BB   8
#define NT   2
#define NN   2000
#define ENN  4000
#define NNZE 32000
#define LL   8
#define DD   64
#define LD   512
#define SEG  (BB*NT)
#define NPB  8             // nodes per block -> M = 64
#define NBLK (NN/NPB)      // 250
#define KD   192
#define BCAP 64            // bucket capacity; Poisson(16) => P(>64) ~ 1e-20

// A smem: 64 rows x 200 bf16 slots (400 B/row, 192 used). hi then lo.
#define AROW 200
#define A_BYTES (64 * AROW * 2)      // 25600
#define SMEM_TOTAL (2 * A_BYTES)

#define STATE_ELEMS ((size_t)BB * ENN * LD)    // 16,384,000 per tensor
#define CONV_PER (int)(STATE_ELEMS / 8)        // 2,048,000 threads per tensor

// ---------------- device scratch ----------------
__device__ int   g_cnt [SEG * NN];
__device__ int2  g_bkt [(size_t)SEG * NN * BCAP];   // packed {val bits, col}
__device__ __align__(16) __half g_s16[2 * STATE_ELEMS];   // fp16 state_in | state_out
// W images: [mat(3)][n(64)][k(192)] bf16, hi and lo
__device__ __align__(16) __nv_bfloat16 g_Wb_hi[3 * 64 * 192];
__device__ __align__(16) __nv_bfloat16 g_Wb_lo[3 * 64 * 192];

// ---------------- helpers ----------------
__device__ __forceinline__ uint32_t smem_u32(const void* p) {
    uint32_t a;
    asm("{ .reg .u64 t; cvta.to.shared.u64 t, %1; cvt.u32.u64 %0, t; }" : "=r"(a) : "l"(p));
    return a;
}
__device__ __forceinline__ float sigm(float x) { return 1.0f / (1.0f + __expf(-x)); }

#define LDMATRIX_X4(r0, r1, r2, r3, addr) \
    asm volatile("ldmatrix.sync.aligned.m8n8.x4.shared.b16 {%0,%1,%2,%3}, [%4];" \
        : "=r"(r0), "=r"(r1), "=r"(r2), "=r"(r3) : "r"(addr))

#define MMA16816(c, a0, a1, a2, a3, b0, b1) \
    asm volatile("mma.sync.aligned.m16n8k16.row.col.f32.bf16.bf16.f32 " \
        "{%0,%1,%2,%3}, {%4,%5,%6,%7}, {%8,%9}, {%0,%1,%2,%3};" \
        : "+f"((c)[0]), "+f"((c)[1]), "+f"((c)[2]), "+f"((c)[3]) \
        : "r"(a0), "r"(a1), "r"(a2), "r"(a3), "r"(b0), "r"(b1))

// fp16-row FMA: 8 halves (one uint4) scaled into 8 fp32 accumulators
__device__ __forceinline__ void fma8(float* a, const uint4& p, float v) {
    const __half2* h = reinterpret_cast<const __half2*>(&p);
#pragma unroll
    for (int q = 0; q < 4; ++q) {
        float2 f = __half22float2(h[q]);
        a[2 * q]     += v * f.x;
        a[2 * q + 1] += v * f.y;
    }
}

// pack 8 fp32 -> bf16 hi uint4 + lo uint4
__device__ __forceinline__ void pack_hilo(const float* a, uint4& hw, uint4& lw) {
    uint32_t* hp = reinterpret_cast<uint32_t*>(&hw);
    uint32_t* lp = reinterpret_cast<uint32_t*>(&lw);
#pragma unroll
    for (int q = 0; q < 4; ++q) {
        __nv_bfloat162 h2 = __floats2bfloat162_rn(a[2 * q], a[2 * q + 1]);
        __nv_bfloat162 l2 = __floats2bfloat162_rn(a[2 * q]     - __bfloat162float(h2.x),
                                                  a[2 * q + 1] - __bfloat162float(h2.y));
        hp[q] = *reinterpret_cast<uint32_t*>(&h2);
        lp[q] = *reinterpret_cast<uint32_t*>(&l2);
    }
}

// ---------------- init: fp16 state conversion + zero counts + W prep ----------------
__global__ void k_init(const float* __restrict__ state_in,
                       const float* __restrict__ state_out,
                       const float* __restrict__ Wr,
                       const float* __restrict__ Wz,
                       const float* __restrict__ Wh) {
    int idx = blockIdx.x * blockDim.x + threadIdx.x;
    if (idx < 2 * CONV_PER) {
        const bool second = (idx >= CONV_PER);
        const float* src = second ? state_out : state_in;
        const size_t base = (size_t)(second ? idx - CONV_PER : idx) * 8;
        __half* dst = g_s16 + (second ? STATE_ELEMS : 0) + base;
        float4 x0 = __ldg(reinterpret_cast<const float4*>(src + base));
        float4 x1 = __ldg(reinterpret_cast<const float4*>(src + base) + 1);
        uint4 o;
        __half2 h;
        h = __floats2half2_rn(x0.x, x0.y); o.x = *reinterpret_cast<uint32_t*>(&h);
        h = __floats2half2_rn(x0.z, x0.w); o.y = *reinterpret_cast<uint32_t*>(&h);
        h = __floats2half2_rn(x1.x, x1.y); o.z = *reinterpret_cast<uint32_t*>(&h);
        h = __floats2half2_rn(x1.z, x1.w); o.w = *reinterpret_cast<uint32_t*>(&h);
        *reinterpret_cast<uint4*>(dst) = o;
    }
    if (idx < SEG * NN) g_cnt[idx] = 0;
    if (idx < 3 * 64 * 192) {
        int mat = idx / (64 * 192);
        int r   = idx - mat * (64 * 192);
        const float* W = (mat == 0) ? Wr : (mat == 1) ? Wz : Wh;
        float w = W[r];
        __nv_bfloat16 hi = __float2bfloat16(w);
        __nv_bfloat16 lo = __float2bfloat16(w - __bfloat162float(hi));
        g_Wb_hi[idx] = hi;
        g_Wb_lo[idx] = lo;
    }
}

// ---------------- single-pass bucketed edge build ----------------
__global__ void k_scatter(const float* __restrict__ vals,
                          const int*   __restrict__ rows,
                          const int*   __restrict__ cols) {
    int idx = blockIdx.x * blockDim.x + threadIdx.x;
    if (idx >= SEG * NNZE) return;
    int seg = idx / NNZE;
    int slot = seg * NN + rows[idx];
    int pos = atomicAdd(&g_cnt[slot], 1);
    if (pos < BCAP)
        g_bkt[(size_t)slot * BCAP + pos] = make_int2(__float_as_int(vals[idx]), cols[idx]);
}

// ---------------- main fused kernel ----------------
__global__ void __launch_bounds__(256)
k_main(const float* __restrict__ state_cur,
       const float* __restrict__ b_r,
       const float* __restrict__ b_z,
       const float* __restrict__ b_h,
       float* __restrict__ out) {
    extern __shared__ char smem[];
    __nv_bfloat16* Ah = reinterpret_cast<__nv_bfloat16*>(smem);
    __nv_bfloat16* Al = reinterpret_cast<__nv_bfloat16*>(smem + A_BYTES);
    const uint32_t sbh = smem_u32(smem);
    const uint32_t sbl = sbh + A_BYTES;

    const int tid  = threadIdx.x;
    const int w    = tid >> 5;
    const int lane = tid & 31;
    const int b    = blockIdx.x / NBLK;
    const int nb   = (blockIdx.x - b * NBLK) * NPB;

    // ---------- Phase 1: SpMM gather over fp16 state, 4 edges/stage (MLP=8) ----------
    for (int task = w; task < 16; task += 8) {
        const int node = task >> 1;
        const int type = task & 1;
        const int n    = nb + node;
        const int seg  = b * NT + type;
        const int slot = seg * NN + n;
        const __half* S = g_s16 + (type ? STATE_ELEMS : 0) + (size_t)b * ENN * LD;
        const int2*  E  = g_bkt + (size_t)slot * BCAP;
        int rem = g_cnt[slot];
        if (rem > BCAP) rem = BCAP;

        float acc0[8], acc1[8];
#pragma unroll
        for (int q = 0; q < 8; ++q) { acc0[q] = 0.0f; acc1[q] = 0.0f; }

        if (rem > 0) {
            float v[4];
            uint4 p0[4], p1[4];
            // prologue: group 0 (clamped indices, zeroed vals past rem)
#pragma unroll
            for (int j = 0; j < 4; ++j) {
                const int ij = (j < rem) ? j : (rem - 1);
                int2 e = __ldg(&E[ij]);
                v[j] = (j < rem) ? __int_as_float(e.x) : 0.0f;
                const uint4* rp = reinterpret_cast<const uint4*>(S + (size_t)e.y * LD);
                p0[j] = __ldg(rp + lane);
                p1[j] = __ldg(rp + 32 + lane);
            }
            for (int i = 0; i < rem; i += 4) {
                // prefetch meta for group i+4
                float nv[4];
                int   nc[4];
#pragma unroll
                for (int j = 0; j < 4; ++j) {
                    const int gj = i + 4 + j;
                    const int ij = (gj < rem) ? gj : (rem - 1);
                    int2 e = __ldg(&E[ij]);
                    nv[j] = (gj < rem) ? __int_as_float(e.x) : 0.0f;
                    nc[j] = e.y;
                }
                // consume current group
#pragma unroll
                for (int j = 0; j < 4; ++j) {
                    fma8(acc0, p0[j], v[j]);
                    fma8(acc1, p1[j], v[j]);
                }
                // load rows for next group (overlaps next iter's FMAs)
#pragma unroll
                for (int j = 0; j < 4; ++j) {
                    const uint4* rp = reinterpret_cast<const uint4*>(S + (size_t)nc[j] * LD);
                    p0[j] = __ldg(rp + lane);
                    p1[j] = __ldg(rp + 32 + lane);
                    v[j]  = nv[j];
                }
            }
        }

        // acc0 -> row l = lane>>3, cols [(lane&7)*8, +8); acc1 -> row +4
        const int l0 = lane >> 3;
        const int d0 = (lane & 7) * 8;
        const int kb = type * DD + d0;
        uint4 hw, lw;
        pack_hilo(acc0, hw, lw);
        {
            const int row = node * LL + l0;
            *reinterpret_cast<uint4*>(&Ah[row * AROW + kb]) = hw;
            *reinterpret_cast<uint4*>(&Al[row * AROW + kb]) = lw;
        }
        pack_hilo(acc1, hw, lw);
        {
            const int row = node * LL + 4 + l0;
            *reinterpret_cast<uint4*>(&Ah[row * AROW + kb]) = hw;
            *reinterpret_cast<uint4*>(&Al[row * AROW + kb]) = lw;
        }
    }
    // state_cur (fp32): warp w loads node w
    {
        const int n = nb + w;
        const float4* C = reinterpret_cast<const float4*>(state_cur + (size_t)(b * NN + n) * LD);
#pragma unroll
        for (int j = 0; j < 4; ++j) {
            const int Eidx = j * 32 + lane;
            const int l    = Eidx >> 4;
            const int d4   = (Eidx & 15) * 4;
            float4 vx = __ldg(C + Eidx);
            const int row = w * LL + l;
            const int kb  = 128 + d4;
            __nv_bfloat162 h01 = __floats2bfloat162_rn(vx.x, vx.y);
            __nv_bfloat162 h23 = __floats2bfloat162_rn(vx.z, vx.w);
            __nv_bfloat162 l01 = __floats2bfloat162_rn(vx.x - __bfloat162float(h01.x),
                                                       vx.y - __bfloat162float(h01.y));
            __nv_bfloat162 l23 = __floats2bfloat162_rn(vx.z - __bfloat162float(h23.x),
                                                       vx.w - __bfloat162float(h23.y));
            uint2 hw, lw;
            hw.x = *reinterpret_cast<uint32_t*>(&h01);
            hw.y = *reinterpret_cast<uint32_t*>(&h23);
            lw.x = *reinterpret_cast<uint32_t*>(&l01);
            lw.y = *reinterpret_cast<uint32_t*>(&l23);
            *reinterpret_cast<uint2*>(&Ah[row * AROW + kb]) = hw;
            *reinterpret_cast<uint2*>(&Al[row * AROW + kb]) = lw;
        }
    }
    __syncthreads();

    // ---------- Phase 2: HMMA GEMMs ----------
    const int n0 = w * 8;
    const int qr = lane >> 2;
    const int qc = (lane & 3) * 2;

    float cr[16], cz[16], ch[16];
#pragma unroll
    for (int i = 0; i < 16; ++i) { cr[i] = 0.0f; cz[i] = 0.0f; ch[i] = 0.0f; }

    const int arow = lane & 15;
    const int koff16 = ((lane >> 4) & 1) * 16;
    const int bnr = (n0 + qr) * 192 + qc;

#pragma unroll
    for (int kt = 0; kt < 8; ++kt) {
        const int k0 = kt * 16;
        const uint32_t brh0 = *reinterpret_cast<const uint32_t*>(g_Wb_hi + bnr + k0);
        const uint32_t brh1 = *reinterpret_cast<const uint32_t*>(g_Wb_hi + bnr + k0 + 8);
        const uint32_t brl0 = *reinterpret_cast<const uint32_t*>(g_Wb_lo + bnr + k0);
        const uint32_t brl1 = *reinterpret_cast<const uint32_t*>(g_Wb_lo + bnr + k0 + 8);
        const uint32_t bzh0 = *reinterpret_cast<const uint32_t*>(g_Wb_hi + 64*192 + bnr + k0);
        const uint32_t bzh1 = *reinterpret_cast<const uint32_t*>(g_Wb_hi + 64*192 + bnr + k0 + 8);
        const uint32_t bzl0 = *reinterpret_cast<const uint32_t*>(g_Wb_lo + 64*192 + bnr + k0);
        const uint32_t bzl1 = *reinterpret_cast<const uint32_t*>(g_Wb_lo + 64*192 + bnr + k0 + 8);
        const uint32_t bhh0 = *reinterpret_cast<const uint32_t*>(g_Wb_hi + 128*192 + bnr + k0);
        const uint32_t bhh1 = *reinterpret_cast<const uint32_t*>(g_Wb_hi + 128*192 + bnr + k0 + 8);
        const uint32_t bhl0 = *reinterpret_cast<const uint32_t*>(g_Wb_lo + 128*192 + bnr + k0);
        const uint32_t bhl1 = *reinterpret_cast<const uint32_t*>(g_Wb_lo + 128*192 + bnr + k0 + 8);
#pragma unroll
        for (int i = 0; i < 4; ++i) {
            const uint32_t aoff = (uint32_t)((16 * i + arow) * 400 + k0 * 2 + koff16);
            uint32_t ah0, ah1, ah2, ah3, al0, al1, al2, al3;
            LDMATRIX_X4(ah0, ah1, ah2, ah3, sbh + aoff);
            LDMATRIX_X4(al0, al1, al2, al3, sbl + aoff);
            MMA16816(cr + 4*i, ah0, ah1, ah2, ah3, brh0, brh1);
            MMA16816(cr + 4*i, al0, al1, al2, al3, brh0, brh1);
            MMA16816(cr + 4*i, ah0, ah1, ah2, ah3, brl0, brl1);
            MMA16816(cz + 4*i, ah0, ah1, ah2, ah3, bzh0, bzh1);
            MMA16816(cz + 4*i, al0, al1, al2, al3, bzh0, bzh1);
            MMA16816(cz + 4*i, ah0, ah1, ah2, ah3, bzl0, bzl1);
            MMA16816(ch + 4*i, ah0, ah1, ah2, ah3, bhh0, bhh1);
            MMA16816(ch + 4*i, al0, al1, al2, al3, bhh0, bhh1);
            MMA16816(ch + 4*i, ah0, ah1, ah2, ah3, bhl0, bhl1);
        }
    }
#pragma unroll
    for (int kt = 8; kt < 12; ++kt) {
        const int k0 = kt * 16;
        const uint32_t brh0 = *reinterpret_cast<const uint32_t*>(g_Wb_hi + bnr + k0);
        const uint32_t brh1 = *reinterpret_cast<const uint32_t*>(g_Wb_hi + bnr + k0 + 8);
        const uint32_t brl0 = *reinterpret_cast<const uint32_t*>(g_Wb_lo + bnr + k0);
        const uint32_t brl1 = *reinterpret_cast<const uint32_t*>(g_Wb_lo + bnr + k0 + 8);
        const uint32_t bzh0 = *reinterpret_cast<const uint32_t*>(g_Wb_hi + 64*192 + bnr + k0);
        const uint32_t bzh1 = *reinterpret_cast<const uint32_t*>(g_Wb_hi + 64*192 + bnr + k0 + 8);
        const uint32_t bzl0 = *reinterpret_cast<const uint32_t*>(g_Wb_lo + 64*192 + bnr + k0);
        const uint32_t bzl1 = *reinterpret_cast<const uint32_t*>(g_Wb_lo + 64*192 + bnr + k0 + 8);
#pragma unroll
        for (int i = 0; i < 4; ++i) {
            const uint32_t aoff = (uint32_t)((16 * i + arow) * 400 + k0 * 2 + koff16);
            uint32_t ah0, ah1, ah2, ah3, al0, al1, al2, al3;
            LDMATRIX_X4(ah0, ah1, ah2, ah3, sbh + aoff);
            LDMATRIX_X4(al0, al1, al2, al3, sbl + aoff);
            MMA16816(cr + 4*i, ah0, ah1, ah2, ah3, brh0, brh1);
            MMA16816(cr + 4*i, al0, al1, al2, al3, brh0, brh1);
            MMA16816(cr + 4*i, ah0, ah1, ah2, ah3, brl0, brl1);
            MMA16816(cz + 4*i, ah0, ah1, ah2, ah3, bzh0, bzh1);
            MMA16816(cz + 4*i, al0, al1, al2, al3, bzh0, bzh1);
            MMA16816(cz + 4*i, ah0, ah1, ah2, ah3, bzl0, bzl1);
        }
    }
    __syncthreads();

    // ---------- Epilogue 1: r, z; write rc = r*cur over cur columns ----------
    float curv[16], zreg[16];
#pragma unroll
    for (int i = 0; i < 4; ++i) {
#pragma unroll
        for (int rr = 0; rr < 2; ++rr) {
            const int m = 16 * i + qr + 8 * rr;
#pragma unroll
            for (int cc = 0; cc < 2; ++cc) {
                const int o   = n0 + qc + cc;
                const int idx = i * 4 + rr * 2 + cc;
                const int e   = m * AROW + 128 + o;
                const float cur = __bfloat162float(Ah[e]) + __bfloat162float(Al[e]);
                curv[idx] = cur;
                const float rv = sigm(cr[idx] + __ldg(&b_r[o]));
                zreg[idx] = sigm(cz[idx] + __ldg(&b_z[o]));
                const float rc = rv * cur;
                const __nv_bfloat16 hi = __float2bfloat16(rc);
                Ah[e] = hi;
                Al[e] = __float2bfloat16(rc - __bfloat162float(hi));
            }
        }
    }
    __syncthreads();

    // ---------- Phase 3: finish h with rc columns ----------
#pragma unroll
    for (int kt = 8; kt < 12; ++kt) {
        const int k0 = kt * 16;
        const uint32_t bhh0 = *reinterpret_cast<const uint32_t*>(g_Wb_hi + 128*192 + bnr + k0);
        const uint32_t bhh1 = *reinterpret_cast<const uint32_t*>(g_Wb_hi + 128*192 + bnr + k0 + 8);
        const uint32_t bhl0 = *reinterpret_cast<const uint32_t*>(g_Wb_lo + 128*192 + bnr + k0);
        const uint32_t bhl1 = *reinterpret_cast<const uint32_t*>(g_Wb_lo + 128*192 + bnr + k0 + 8);
#pragma unroll
        for (int i = 0; i < 4; ++i) {
            const uint32_t aoff = (uint32_t)((16 * i + arow) * 400 + k0 * 2 + koff16);
            uint32_t ah0, ah1, ah2, ah3, al0, al1, al2, al3;
            LDMATRIX_X4(ah0, ah1, ah2, ah3, sbh + aoff);
            LDMATRIX_X4(al0, al1, al2, al3, sbl + aoff);
            MMA16816(ch + 4*i, ah0, ah1, ah2, ah3, bhh0, bhh1);
            MMA16816(ch + 4*i, al0, al1, al2, al3, bhh0, bhh1);
            MMA16816(ch + 4*i, ah0, ah1, ah2, ah3, bhl0, bhl1);
        }
    }

    // ---------- Epilogue 2: GRU combine + store ----------
#pragma unroll
    for (int i = 0; i < 4; ++i) {
#pragma unroll
        for (int rr = 0; rr < 2; ++rr) {
            const int m    = 16 * i + qr + 8 * rr;
            const int node = m >> 3;
            const int l    = m & 7;
            const size_t grow = ((size_t)(b * NN + nb + node) * LL + l);
            float2 v;
#pragma unroll
            for (int cc = 0; cc < 2; ++cc) {
                const int o   = n0 + qc + cc;
                const int idx = i * 4 + rr * 2 + cc;
                const float h = tanhf(ch[idx] + __ldg(&b_h[o]));
                const float z = zreg[idx];
                const float r2 = (1.0f - z) * curv[idx] + z * h;
                if (cc == 0) v.x = r2; else v.y = r2;
            }
            *reinterpret_cast<float2*>(out + grow * DD + n0 + qc) = v;
        }
    }
}

// ---------------- launch ----------------
extern "C" void kernel_launch(void* const* d_in, const int* in_sizes, int n_in,
                              void* d_out, int out_size) {
    (void)in_sizes; (void)n_in; (void)out_size;
    const float* state_in  = (const float*)d_in[0];
    const float* state_out = (const float*)d_in[1];
    const float* state_cur = (const float*)d_in[2];
    const float* A_vals    = (const float*)d_in[3];
    const int*   A_rows    = (const int*)  d_in[4];
    const int*   A_cols    = (const int*)  d_in[5];
    const float* W_r       = (const float*)d_in[6];
    const float* b_r       = (const float*)d_in[7];
    const float* W_z       = (const float*)d_in[8];
    const float* b_z       = (const float*)d_in[9];
    const float* W_h       = (const float*)d_in[10];
    const float* b_h       = (const float*)d_in[11];
    float* out = (float*)d_out;

    cudaFuncSetAttribute(k_main, cudaFuncAttributeMaxDynamicSharedMemorySize, SMEM_TOTAL);

    k_init<<<(2 * CONV_PER + 255) / 256, 256>>>(state_in, state_out, W_r, W_z, W_h);
    k_scatter<<<(SEG * NNZE + 255) / 256, 256>>>(A_vals, A_rows, A_cols);
    k_main<<<BB * NBLK, 256, SMEM_TOTAL>>>(state_cur, b_r, b_z, b_h, out);
}

// round 13
// speedup vs baseline: 1.4689x; 1.4304x over previous
#include <cuda_runtime.h>
#include <cuda_fp16.h>
#include <cstdint>

// ---------------- problem constants ----------------
#define BB   8
#define NT   2
#define NN   2000
#define ENN  4000
#define NNZE 32000
#define LL   8
#define DD   64
#define LD   512
#define SEG  (BB*NT)
#define NPB  8             // nodes per block -> M = 64
#define NBLK (NN/NPB)      // 250
#define KD   192
#define BCAP 64            // bucket capacity; Poisson(16) => P(>64) ~ 1e-20

// A smem: 64 rows x 200 fp16 slots (400 B/row, 192 used).
#define AROW 200
#define A_BYTES (64 * AROW * 2)      // 25600
#define SMEM_TOTAL A_BYTES

// ---------------- device scratch ----------------
__device__ int   g_cnt [SEG * NN];
__device__ int2  g_bkt [(size_t)SEG * NN * BCAP];   // packed {val bits, col}
// W image: [mat(3)][n(64)][k(192)] fp16
__device__ __align__(16) __half g_W16[3 * 64 * 192];

// ---------------- helpers ----------------
__device__ __forceinline__ uint32_t smem_u32(const void* p) {
    uint32_t a;
    asm("{ .reg .u64 t; cvta.to.shared.u64 t, %1; cvt.u32.u64 %0, t; }" : "=r"(a) : "l"(p));
    return a;
}
__device__ __forceinline__ float sigm(float x) { return 1.0f / (1.0f + __expf(-x)); }

#define LDMATRIX_X4(r0, r1, r2, r3, addr) \
    asm volatile("ldmatrix.sync.aligned.m8n8.x4.shared.b16 {%0,%1,%2,%3}, [%4];" \
        : "=r"(r0), "=r"(r1), "=r"(r2), "=r"(r3) : "r"(addr))

#define MMA16816F16(c, a0, a1, a2, a3, b0, b1) \
    asm volatile("mma.sync.aligned.m16n8k16.row.col.f32.f16.f16.f32 " \
        "{%0,%1,%2,%3}, {%4,%5,%6,%7}, {%8,%9}, {%0,%1,%2,%3};" \
        : "+f"((c)[0]), "+f"((c)[1]), "+f"((c)[2]), "+f"((c)[3]) \
        : "r"(a0), "r"(a1), "r"(a2), "r"(a3), "r"(b0), "r"(b1))

// ---------------- init: zero counts + W fp16 prep ----------------
__global__ void k_init(const float* __restrict__ Wr,
                       const float* __restrict__ Wz,
                       const float* __restrict__ Wh) {
    int idx = blockIdx.x * blockDim.x + threadIdx.x;
    if (idx < SEG * NN) g_cnt[idx] = 0;
    if (idx < 3 * 64 * 192) {
        int mat = idx / (64 * 192);
        int r   = idx - mat * (64 * 192);
        const float* W = (mat == 0) ? Wr : (mat == 1) ? Wz : Wh;
        g_W16[idx] = __float2half(W[r]);
    }
}

// ---------------- single-pass bucketed edge build ----------------
__global__ void k_scatter(const float* __restrict__ vals,
                          const int*   __restrict__ rows,
                          const int*   __restrict__ cols) {
    int idx = blockIdx.x * blockDim.x + threadIdx.x;
    if (idx >= SEG * NNZE) return;
    int seg = idx / NNZE;
    int slot = seg * NN + rows[idx];
    int pos = atomicAdd(&g_cnt[slot], 1);
    if (pos < BCAP)
        g_bkt[(size_t)slot * BCAP + pos] = make_int2(__float_as_int(vals[idx]), cols[idx]);
}

// ---------------- main fused kernel ----------------
__global__ void __launch_bounds__(256)
k_main(const float* __restrict__ state_in,
       const float* __restrict__ state_out,
       const float* __restrict__ state_cur,
       const float* __restrict__ b_r,
       const float* __restrict__ b_z,
       const float* __restrict__ b_h,
       float* __restrict__ out) {
    extern __shared__ char smem[];
    __half* As = reinterpret_cast<__half*>(smem);
    const uint32_t sbh = smem_u32(smem);

    const int tid  = threadIdx.x;
    const int w    = tid >> 5;
    const int lane = tid & 31;
    const int b    = blockIdx.x / NBLK;
    const int nb   = (blockIdx.x - b * NBLK) * NPB;

    // ---------- Phase 1: SpMM gather (fp32, pipelined dist-2) ----------
    for (int task = w; task < 16; task += 8) {
        const int node = task >> 1;
        const int type = task & 1;
        const int n    = nb + node;
        const int seg  = b * NT + type;
        const int slot = seg * NN + n;
        const float* S  = (type == 0 ? state_in : state_out) + (size_t)b * ENN * LD;
        const int2*  E  = g_bkt + (size_t)slot * BCAP;
        int rem = g_cnt[slot];
        if (rem > BCAP) rem = BCAP;

        float4 a0 = {0,0,0,0}, a1 = {0,0,0,0}, a2 = {0,0,0,0}, a3 = {0,0,0,0};

        if (rem > 0) {
            int2 e0 = __ldg(&E[0]);
            int2 e1 = __ldg(&E[(rem > 1) ? 1 : 0]);
            const float4* r0p = reinterpret_cast<const float4*>(S + (size_t)e0.y * LD);
            const float4* r1p = reinterpret_cast<const float4*>(S + (size_t)e1.y * LD);
            float4 p00 = __ldg(r0p + lane);
            float4 p01 = __ldg(r0p + 32 + lane);
            float4 p02 = __ldg(r0p + 64 + lane);
            float4 p03 = __ldg(r0p + 96 + lane);
            float4 p10 = __ldg(r1p + lane);
            float4 p11 = __ldg(r1p + 32 + lane);
            float4 p12 = __ldg(r1p + 64 + lane);
            float4 p13 = __ldg(r1p + 96 + lane);

            int i = 0;
            while (i + 2 <= rem) {
                const int i2 = (i + 2 < rem) ? (i + 2) : (rem - 1);
                const int i3 = (i + 3 < rem) ? (i + 3) : (rem - 1);
                int2 f0 = __ldg(&E[i2]);
                int2 f1 = __ldg(&E[i3]);

                const float va = __int_as_float(e0.x);
                const float vb = __int_as_float(e1.x);

                a0.x += va * p00.x; a0.y += va * p00.y; a0.z += va * p00.z; a0.w += va * p00.w;
                a1.x += va * p01.x; a1.y += va * p01.y; a1.z += va * p01.z; a1.w += va * p01.w;
                a2.x += va * p02.x; a2.y += va * p02.y; a2.z += va * p02.z; a2.w += va * p02.w;
                a3.x += va * p03.x; a3.y += va * p03.y; a3.z += va * p03.z; a3.w += va * p03.w;
                a0.x += vb * p10.x; a0.y += vb * p10.y; a0.z += vb * p10.z; a0.w += vb * p10.w;
                a1.x += vb * p11.x; a1.y += vb * p11.y; a1.z += vb * p11.z; a1.w += vb * p11.w;
                a2.x += vb * p12.x; a2.y += vb * p12.y; a2.z += vb * p12.z; a2.w += vb * p12.w;
                a3.x += vb * p13.x; a3.y += vb * p13.y; a3.z += vb * p13.z; a3.w += vb * p13.w;

                const float4* q0p = reinterpret_cast<const float4*>(S + (size_t)f0.y * LD);
                const float4* q1p = reinterpret_cast<const float4*>(S + (size_t)f1.y * LD);
                p00 = __ldg(q0p + lane);
                p01 = __ldg(q0p + 32 + lane);
                p02 = __ldg(q0p + 64 + lane);
                p03 = __ldg(q0p + 96 + lane);
                p10 = __ldg(q1p + lane);
                p11 = __ldg(q1p + 32 + lane);
                p12 = __ldg(q1p + 64 + lane);
                p13 = __ldg(q1p + 96 + lane);

                e0 = f0; e1 = f1;
                i += 2;
            }
            if (i < rem) {
                const float va = __int_as_float(e0.x);
                a0.x += va * p00.x; a0.y += va * p00.y; a0.z += va * p00.z; a0.w += va * p00.w;
                a1.x += va * p01.x; a1.y += va * p01.y; a1.z += va * p01.z; a1.w += va * p01.w;
                a2.x += va * p02.x; a2.y += va * p02.y; a2.z += va * p02.z; a2.w += va * p02.w;
                a3.x += va * p03.x; a3.y += va * p03.y; a3.z += va * p03.z; a3.w += va * p03.w;
            }
        }

        float4 acc[4] = {a0, a1, a2, a3};
#pragma unroll
        for (int j = 0; j < 4; ++j) {
            const int Eidx = j * 32 + lane;
            const int l    = Eidx >> 4;
            const int d4   = (Eidx & 15) * 4;
            const int row  = node * LL + l;
            const int kb   = type * DD + d4;
            float4 vx = acc[j];
            __half2 h01 = __floats2half2_rn(vx.x, vx.y);
            __half2 h23 = __floats2half2_rn(vx.z, vx.w);
            uint2 hw;
            hw.x = *reinterpret_cast<uint32_t*>(&h01);
            hw.y = *reinterpret_cast<uint32_t*>(&h23);
            *reinterpret_cast<uint2*>(&As[row * AROW + kb]) = hw;
        }
    }
    // state_cur: warp w loads node w
    {
        const int n = nb + w;
        const float4* C = reinterpret_cast<const float4*>(state_cur + (size_t)(b * NN + n) * LD);
#pragma unroll
        for (int j = 0; j < 4; ++j) {
            const int Eidx = j * 32 + lane;
            const int l    = Eidx >> 4;
            const int d4   = (Eidx & 15) * 4;
            float4 vx = __ldg(C + Eidx);
            const int row = w * LL + l;
            const int kb  = 128 + d4;
            __half2 h01 = __floats2half2_rn(vx.x, vx.y);
            __half2 h23 = __floats2half2_rn(vx.z, vx.w);
            uint2 hw;
            hw.x = *reinterpret_cast<uint32_t*>(&h01);
            hw.y = *reinterpret_cast<uint32_t*>(&h23);
            *reinterpret_cast<uint2*>(&As[row * AROW + kb]) = hw;
        }
    }
    __syncthreads();

    // ---------- Phase 2: fp16 HMMA GEMMs (single term) ----------
    const int n0 = w * 8;
    const int qr = lane >> 2;
    const int qc = (lane & 3) * 2;

    float cr[16], cz[16], ch[16];
#pragma unroll
    for (int i = 0; i < 16; ++i) { cr[i] = 0.0f; cz[i] = 0.0f; ch[i] = 0.0f; }

    const int arow = lane & 15;
    const int koff16 = ((lane >> 4) & 1) * 16;
    const int bnr = (n0 + qr) * 192 + qc;

#pragma unroll
    for (int kt = 0; kt < 8; ++kt) {
        const int k0 = kt * 16;
        const uint32_t br0 = *reinterpret_cast<const uint32_t*>(g_W16 + bnr + k0);
        const uint32_t br1 = *reinterpret_cast<const uint32_t*>(g_W16 + bnr + k0 + 8);
        const uint32_t bz0 = *reinterpret_cast<const uint32_t*>(g_W16 + 64*192 + bnr + k0);
        const uint32_t bz1 = *reinterpret_cast<const uint32_t*>(g_W16 + 64*192 + bnr + k0 + 8);
        const uint32_t bh0 = *reinterpret_cast<const uint32_t*>(g_W16 + 128*192 + bnr + k0);
        const uint32_t bh1 = *reinterpret_cast<const uint32_t*>(g_W16 + 128*192 + bnr + k0 + 8);
#pragma unroll
        for (int i = 0; i < 4; ++i) {
            const uint32_t aoff = (uint32_t)((16 * i + arow) * 400 + k0 * 2 + koff16);
            uint32_t a0, a1, a2, a3;
            LDMATRIX_X4(a0, a1, a2, a3, sbh + aoff);
            MMA16816F16(cr + 4*i, a0, a1, a2, a3, br0, br1);
            MMA16816F16(cz + 4*i, a0, a1, a2, a3, bz0, bz1);
            MMA16816F16(ch + 4*i, a0, a1, a2, a3, bh0, bh1);
        }
    }
#pragma unroll
    for (int kt = 8; kt < 12; ++kt) {
        const int k0 = kt * 16;
        const uint32_t br0 = *reinterpret_cast<const uint32_t*>(g_W16 + bnr + k0);
        const uint32_t br1 = *reinterpret_cast<const uint32_t*>(g_W16 + bnr + k0 + 8);
        const uint32_t bz0 = *reinterpret_cast<const uint32_t*>(g_W16 + 64*192 + bnr + k0);
        const uint32_t bz1 = *reinterpret_cast<const uint32_t*>(g_W16 + 64*192 + bnr + k0 + 8);
#pragma unroll
        for (int i = 0; i < 4; ++i) {
            const uint32_t aoff = (uint32_t)((16 * i + arow) * 400 + k0 * 2 + koff16);
            uint32_t a0, a1, a2, a3;
            LDMATRIX_X4(a0, a1, a2, a3, sbh + aoff);
            MMA16816F16(cr + 4*i, a0, a1, a2, a3, br0, br1);
            MMA16816F16(cz + 4*i, a0, a1, a2, a3, bz0, bz1);
        }
    }
    __syncthreads();

    // ---------- Epilogue 1: r, z; write rc = r*cur over cur columns ----------
    float curv[16], zreg[16];
#pragma unroll
    for (int i = 0; i < 4; ++i) {
#pragma unroll
        for (int rr = 0; rr < 2; ++rr) {
            const int m = 16 * i + qr + 8 * rr;
#pragma unroll
            for (int cc = 0; cc < 2; ++cc) {
                const int o   = n0 + qc + cc;
                const int idx = i * 4 + rr * 2 + cc;
                const int e   = m * AROW + 128 + o;
                const float cur = __half2float(As[e]);
                curv[idx] = cur;
                const float rv = sigm(cr[idx] + __ldg(&b_r[o]));
                zreg[idx] = sigm(cz[idx] + __ldg(&b_z[o]));
                As[e] = __float2half(rv * cur);
            }
        }
    }
    __syncthreads();

    // ---------- Phase 3: finish h with rc columns ----------
#pragma unroll
    for (int kt = 8; kt < 12; ++kt) {
        const int k0 = kt * 16;
        const uint32_t bh0 = *reinterpret_cast<const uint32_t*>(g_W16 + 128*192 + bnr + k0);
        const uint32_t bh1 = *reinterpret_cast<const uint32_t*>(g_W16 + 128*192 + bnr + k0 + 8);
#pragma unroll
        for (int i = 0; i < 4; ++i) {
            const uint32_t aoff = (uint32_t)((16 * i + arow) * 400 + k0 * 2 + koff16);
            uint32_t a0, a1, a2, a3;
            LDMATRIX_X4(a0, a1, a2, a3, sbh + aoff);
            MMA16816F16(ch + 4*i, a0, a1, a2, a3, bh0, bh1);
        }
    }

    // ---------- Epilogue 2: GRU combine + store ----------
#pragma unroll
    for (int i = 0; i < 4; ++i) {
#pragma unroll
        for (int rr = 0; rr < 2; ++rr) {
            const int m    = 16 * i + qr + 8 * rr;
            const int node = m >> 3;
            const int l    = m & 7;
            const size_t grow = ((size_t)(b * NN + nb + node) * LL + l);
            float2 v;
#pragma unroll
            for (int cc = 0; cc < 2; ++cc) {
                const int o   = n0 + qc + cc;
                const int idx = i * 4 + rr * 2 + cc;
                const float h = tanhf(ch[idx] + __ldg(&b_h[o]));
                const float z = zreg[idx];
                const float r2 = (1.0f - z) * curv[idx] + z * h;
                if (cc == 0) v.x = r2; else v.y = r2;
            }
            *reinterpret_cast<float2*>(out + grow * DD + n0 + qc) = v;
        }
    }
}

// ---------------- launch ----------------
extern "C" void kernel_launch(void* const* d_in, const int* in_sizes, int n_in,
                              void* d_out, int out_size) {
    (void)in_sizes; (void)n_in; (void)out_size;
    const float* state_in  = (const float*)d_in[0];
    const float* state_out = (const float*)d_in[1];
    const float* state_cur = (const float*)d_in[2];
    const float* A_vals    = (const float*)d_in[3];
    const int*   A_rows    = (const int*)  d_in[4];
    const int*   A_cols    = (const int*)  d_in[5];
    const float* W_r       = (const float*)d_in[6];
    const float* b_r       = (const float*)d_in[7];
    const float* W_z       = (const float*)d_in[8];
    const float* b_z       = (const float*)d_in[9];
    const float* W_h       = (const float*)d_in[10];
    const float* b_h       = (const float*)d_in[11];
    float* out = (float*)d_out;

    cudaFuncSetAttribute(k_main, cudaFuncAttributeMaxDynamicSharedMemorySize, SMEM_TOTAL);

    k_init<<<(3 * 64 * 192 + 255) / 256, 256>>>(W_r, W_z, W_h);
    k_scatter<<<(SEG * NNZE + 255) / 256, 256>>>(A_vals, A_rows, A_cols);
    k_main<<<BB * NBLK, 256, SMEM_TOTAL>>>(state_in, state_out, state_cur,
                                           b_r, b_z, b_h, out);
}

// round 14
// speedup vs baseline: 1.4878x; 1.0128x over previous
#include <cuda_runtime.h>
#include <cuda_fp16.h>
#include <cstdint>

// ---------------- problem constants ----------------
#define BB   8
#define NT   2
#define NN   2000
#define ENN  4000
#define NNZE 32000
#define LL   8
#define DD   64
#define LD   512
#define SEG  (BB*NT)
#define NPB  8             // nodes per block -> M = 64
#define NBLK (NN/NPB)      // 250
#define KD   192
#define BCAP 64            // bucket capacity; Poisson(16) => P(>64) ~ 1e-20

// A smem: 64 rows x 200 fp16 slots (400 B/row, 192 used).
#define AROW 200
#define A_BYTES (64 * AROW * 2)      // 25600
#define SMEM_TOTAL A_BYTES

// ---------------- device scratch ----------------
__device__ int   g_cnt [SEG * NN];
__device__ int2  g_bkt [(size_t)SEG * NN * BCAP];   // packed {val bits, col}
// W image: [mat(3)][n(64)][k(192)] fp16
__device__ __align__(16) __half g_W16[3 * 64 * 192];

// ---------------- helpers ----------------
__device__ __forceinline__ uint32_t smem_u32(const void* p) {
    uint32_t a;
    asm("{ .reg .u64 t; cvta.to.shared.u64 t, %1; cvt.u32.u64 %0, t; }" : "=r"(a) : "l"(p));
    return a;
}
__device__ __forceinline__ float sigm(float x) { return 1.0f / (1.0f + __expf(-x)); }

#define LDMATRIX_X4(r0, r1, r2, r3, addr) \
    asm volatile("ldmatrix.sync.aligned.m8n8.x4.shared.b16 {%0,%1,%2,%3}, [%4];" \
        : "=r"(r0), "=r"(r1), "=r"(r2), "=r"(r3) : "r"(addr))

#define MMA16816F16(c, a0, a1, a2, a3, b0, b1) \
    asm volatile("mma.sync.aligned.m16n8k16.row.col.f32.f16.f16.f32 " \
        "{%0,%1,%2,%3}, {%4,%5,%6,%7}, {%8,%9}, {%0,%1,%2,%3};" \
        : "+f"((c)[0]), "+f"((c)[1]), "+f"((c)[2]), "+f"((c)[3]) \
        : "r"(a0), "r"(a1), "r"(a2), "r"(a3), "r"(b0), "r"(b1))

// ---------------- init: zero counts + W fp16 prep ----------------
__global__ void k_init(const float* __restrict__ Wr,
                       const float* __restrict__ Wz,
                       const float* __restrict__ Wh) {
    int idx = blockIdx.x * blockDim.x + threadIdx.x;
    if (idx < SEG * NN) g_cnt[idx] = 0;
    if (idx < 3 * 64 * 192) {
        int mat = idx / (64 * 192);
        int r   = idx - mat * (64 * 192);
        const float* W = (mat == 0) ? Wr : (mat == 1) ? Wz : Wh;
        g_W16[idx] = __float2half(W[r]);
    }
}

// ---------------- single-pass bucketed edge build ----------------
__global__ void k_scatter(const float* __restrict__ vals,
                          const int*   __restrict__ rows,
                          const int*   __restrict__ cols) {
    int idx = blockIdx.x * blockDim.x + threadIdx.x;
    if (idx >= SEG * NNZE) return;
    int seg = idx / NNZE;
    int slot = seg * NN + rows[idx];
    int pos = atomicAdd(&g_cnt[slot], 1);
    if (pos < BCAP)
        g_bkt[(size_t)slot * BCAP + pos] = make_int2(__float_as_int(vals[idx]), cols[idx]);
}

// ---------------- main fused kernel ----------------
__global__ void __launch_bounds__(256, 3)
k_main(const float* __restrict__ state_in,
       const float* __restrict__ state_out,
       const float* __restrict__ state_cur,
       const float* __restrict__ b_r,
       const float* __restrict__ b_z,
       const float* __restrict__ b_h,
       float* __restrict__ out) {
    extern __shared__ char smem[];
    __half* As = reinterpret_cast<__half*>(smem);
    const uint32_t sbh = smem_u32(smem);

    const int tid  = threadIdx.x;
    const int w    = tid >> 5;
    const int lane = tid & 31;
    const int b    = blockIdx.x / NBLK;
    const int nb   = (blockIdx.x - b * NBLK) * NPB;

    // ---------- Phase 1: SpMM gather (fp32, pipelined dist-2) ----------
    for (int task = w; task < 16; task += 8) {
        const int node = task >> 1;
        const int type = task & 1;
        const int n    = nb + node;
        const int seg  = b * NT + type;
        const int slot = seg * NN + n;
        const float* S  = (type == 0 ? state_in : state_out) + (size_t)b * ENN * LD;
        const int2*  E  = g_bkt + (size_t)slot * BCAP;
        int rem = g_cnt[slot];
        if (rem > BCAP) rem = BCAP;

        float4 a0 = {0,0,0,0}, a1 = {0,0,0,0}, a2 = {0,0,0,0}, a3 = {0,0,0,0};

        if (rem > 0) {
            int2 e0 = __ldg(&E[0]);
            int2 e1 = __ldg(&E[(rem > 1) ? 1 : 0]);
            const float4* r0p = reinterpret_cast<const float4*>(S + (size_t)e0.y * LD);
            const float4* r1p = reinterpret_cast<const float4*>(S + (size_t)e1.y * LD);
            float4 p00 = __ldg(r0p + lane);
            float4 p01 = __ldg(r0p + 32 + lane);
            float4 p02 = __ldg(r0p + 64 + lane);
            float4 p03 = __ldg(r0p + 96 + lane);
            float4 p10 = __ldg(r1p + lane);
            float4 p11 = __ldg(r1p + 32 + lane);
            float4 p12 = __ldg(r1p + 64 + lane);
            float4 p13 = __ldg(r1p + 96 + lane);

            int i = 0;
            while (i + 2 <= rem) {
                const int i2 = (i + 2 < rem) ? (i + 2) : (rem - 1);
                const int i3 = (i + 3 < rem) ? (i + 3) : (rem - 1);
                int2 f0 = __ldg(&E[i2]);
                int2 f1 = __ldg(&E[i3]);

                const float va = __int_as_float(e0.x);
                const float vb = __int_as_float(e1.x);

                a0.x += va * p00.x; a0.y += va * p00.y; a0.z += va * p00.z; a0.w += va * p00.w;
                a1.x += va * p01.x; a1.y += va * p01.y; a1.z += va * p01.z; a1.w += va * p01.w;
                a2.x += va * p02.x; a2.y += va * p02.y; a2.z += va * p02.z; a2.w += va * p02.w;
                a3.x += va * p03.x; a3.y += va * p03.y; a3.z += va * p03.z; a3.w += va * p03.w;
                a0.x += vb * p10.x; a0.y += vb * p10.y; a0.z += vb * p10.z; a0.w += vb * p10.w;
                a1.x += vb * p11.x; a1.y += vb * p11.y; a1.z += vb * p11.z; a1.w += vb * p11.w;
                a2.x += vb * p12.x; a2.y += vb * p12.y; a2.z += vb * p12.z; a2.w += vb * p12.w;
                a3.x += vb * p13.x; a3.y += vb * p13.y; a3.z += vb * p13.z; a3.w += vb * p13.w;

                const float4* q0p = reinterpret_cast<const float4*>(S + (size_t)f0.y * LD);
                const float4* q1p = reinterpret_cast<const float4*>(S + (size_t)f1.y * LD);
                p00 = __ldg(q0p + lane);
                p01 = __ldg(q0p + 32 + lane);
                p02 = __ldg(q0p + 64 + lane);
                p03 = __ldg(q0p + 96 + lane);
                p10 = __ldg(q1p + lane);
                p11 = __ldg(q1p + 32 + lane);
                p12 = __ldg(q1p + 64 + lane);
                p13 = __ldg(q1p + 96 + lane);

                e0 = f0; e1 = f1;
                i += 2;
            }
            if (i < rem) {
                const float va = __int_as_float(e0.x);
                a0.x += va * p00.x; a0.y += va * p00.y; a0.z += va * p00.z; a0.w += va * p00.w;
                a1.x += va * p01.x; a1.y += va * p01.y; a1.z += va * p01.z; a1.w += va * p01.w;
                a2.x += va * p02.x; a2.y += va * p02.y; a2.z += va * p02.z; a2.w += va * p02.w;
                a3.x += va * p03.x; a3.y += va * p03.y; a3.z += va * p03.z; a3.w += va * p03.w;
            }
        }

        float4 acc[4] = {a0, a1, a2, a3};
#pragma unroll
        for (int j = 0; j < 4; ++j) {
            const int Eidx = j * 32 + lane;
            const int l    = Eidx >> 4;
            const int d4   = (Eidx & 15) * 4;
            const int row  = node * LL + l;
            const int kb   = type * DD + d4;
            float4 vx = acc[j];
            __half2 h01 = __floats2half2_rn(vx.x, vx.y);
            __half2 h23 = __floats2half2_rn(vx.z, vx.w);
            uint2 hw;
            hw.x = *reinterpret_cast<uint32_t*>(&h01);
            hw.y = *reinterpret_cast<uint32_t*>(&h23);
            *reinterpret_cast<uint2*>(&As[row * AROW + kb]) = hw;
        }
    }
    // state_cur: warp w loads node w
    {
        const int n = nb + w;
        const float4* C = reinterpret_cast<const float4*>(state_cur + (size_t)(b * NN + n) * LD);
#pragma unroll
        for (int j = 0; j < 4; ++j) {
            const int Eidx = j * 32 + lane;
            const int l    = Eidx >> 4;
            const int d4   = (Eidx & 15) * 4;
            float4 vx = __ldg(C + Eidx);
            const int row = w * LL + l;
            const int kb  = 128 + d4;
            __half2 h01 = __floats2half2_rn(vx.x, vx.y);
            __half2 h23 = __floats2half2_rn(vx.z, vx.w);
            uint2 hw;
            hw.x = *reinterpret_cast<uint32_t*>(&h01);
            hw.y = *reinterpret_cast<uint32_t*>(&h23);
            *reinterpret_cast<uint2*>(&As[row * AROW + kb]) = hw;
        }
    }
    __syncthreads();

    // ---------- Phase 2: fp16 HMMA GEMMs (single term) ----------
    const int n0 = w * 8;
    const int qr = lane >> 2;
    const int qc = (lane & 3) * 2;

    float cr[16], cz[16], ch[16];
#pragma unroll
    for (int i = 0; i < 16; ++i) { cr[i] = 0.0f; cz[i] = 0.0f; ch[i] = 0.0f; }

    const int arow = lane & 15;
    const int koff16 = ((lane >> 4) & 1) * 16;
    const int bnr = (n0 + qr) * 192 + qc;

#pragma unroll
    for (int kt = 0; kt < 8; ++kt) {
        const int k0 = kt * 16;
        const uint32_t br0 = *reinterpret_cast<const uint32_t*>(g_W16 + bnr + k0);
        const uint32_t br1 = *reinterpret_cast<const uint32_t*>(g_W16 + bnr + k0 + 8);
        const uint32_t bz0 = *reinterpret_cast<const uint32_t*>(g_W16 + 64*192 + bnr + k0);
        const uint32_t bz1 = *reinterpret_cast<const uint32_t*>(g_W16 + 64*192 + bnr + k0 + 8);
        const uint32_t bh0 = *reinterpret_cast<const uint32_t*>(g_W16 + 128*192 + bnr + k0);
        const uint32_t bh1 = *reinterpret_cast<const uint32_t*>(g_W16 + 128*192 + bnr + k0 + 8);
#pragma unroll
        for (int i = 0; i < 4; ++i) {
            const uint32_t aoff = (uint32_t)((16 * i + arow) * 400 + k0 * 2 + koff16);
            uint32_t a0, a1, a2, a3;
            LDMATRIX_X4(a0, a1, a2, a3, sbh + aoff);
            MMA16816F16(cr + 4*i, a0, a1, a2, a3, br0, br1);
            MMA16816F16(cz + 4*i, a0, a1, a2, a3, bz0, bz1);
            MMA16816F16(ch + 4*i, a0, a1, a2, a3, bh0, bh1);
        }
    }
#pragma unroll
    for (int kt = 8; kt < 12; ++kt) {
        const int k0 = kt * 16;
        const uint32_t br0 = *reinterpret_cast<const uint32_t*>(g_W16 + bnr + k0);
        const uint32_t br1 = *reinterpret_cast<const uint32_t*>(g_W16 + bnr + k0 + 8);
        const uint32_t bz0 = *reinterpret_cast<const uint32_t*>(g_W16 + 64*192 + bnr + k0);
        const uint32_t bz1 = *reinterpret_cast<const uint32_t*>(g_W16 + 64*192 + bnr + k0 + 8);
#pragma unroll
        for (int i = 0; i < 4; ++i) {
            const uint32_t aoff = (uint32_t)((16 * i + arow) * 400 + k0 * 2 + koff16);
            uint32_t a0, a1, a2, a3;
            LDMATRIX_X4(a0, a1, a2, a3, sbh + aoff);
            MMA16816F16(cr + 4*i, a0, a1, a2, a3, br0, br1);
            MMA16816F16(cz + 4*i, a0, a1, a2, a3, bz0, bz1);
        }
    }
    __syncthreads();

    // ---------- Epilogue 1: r, z; write rc = r*cur over cur columns ----------
    float curv[16], zreg[16];
#pragma unroll
    for (int i = 0; i < 4; ++i) {
#pragma unroll
        for (int rr = 0; rr < 2; ++rr) {
            const int m = 16 * i + qr + 8 * rr;
#pragma unroll
            for (int cc = 0; cc < 2; ++cc) {
                const int o   = n0 + qc + cc;
                const int idx = i * 4 + rr * 2 + cc;
                const int e   = m * AROW + 128 + o;
                const float cur = __half2float(As[e]);
                curv[idx] = cur;
                const float rv = sigm(cr[idx] + __ldg(&b_r[o]));
                zreg[idx] = sigm(cz[idx] + __ldg(&b_z[o]));
                As[e] = __float2half(rv * cur);
            }
        }
    }
    __syncthreads();

    // ---------- Phase 3: finish h with rc columns ----------
#pragma unroll
    for (int kt = 8; kt < 12; ++kt) {
        const int k0 = kt * 16;
        const uint32_t bh0 = *reinterpret_cast<const uint32_t*>(g_W16 + 128*192 + bnr + k0);
        const uint32_t bh1 = *reinterpret_cast<const uint32_t*>(g_W16 + 128*192 + bnr + k0 + 8);
#pragma unroll
        for (int i = 0; i < 4; ++i) {
            const uint32_t aoff = (uint32_t)((16 * i + arow) * 400 + k0 * 2 + koff16);
            uint32_t a0, a1, a2, a3;
            LDMATRIX_X4(a0, a1, a2, a3, sbh + aoff);
            MMA16816F16(ch + 4*i, a0, a1, a2, a3, bh0, bh1);
        }
    }

    // ---------- Epilogue 2: GRU combine + store ----------
#pragma unroll
    for (int i = 0; i < 4; ++i) {
#pragma unroll
        for (int rr = 0; rr < 2; ++rr) {
            const int m    = 16 * i + qr + 8 * rr;
            const int node = m >> 3;
            const int l    = m & 7;
            const size_t grow = ((size_t)(b * NN + nb + node) * LL + l);
            float2 v;
#pragma unroll
            for (int cc = 0; cc < 2; ++cc) {
                const int o   = n0 + qc + cc;
                const int idx = i * 4 + rr * 2 + cc;
                const float h = tanhf(ch[idx] + __ldg(&b_h[o]));
                const float z = zreg[idx];
                const float r2 = (1.0f - z) * curv[idx] + z * h;
                if (cc == 0) v.x = r2; else v.y = r2;
            }
            *reinterpret_cast<float2*>(out + grow * DD + n0 + qc) = v;
        }
    }
}

// ---------------- launch ----------------
extern "C" void kernel_launch(void* const* d_in, const int* in_sizes, int n_in,
                              void* d_out, int out_size) {
    (void)in_sizes; (void)n_in; (void)out_size;
    const float* state_in  = (const float*)d_in[0];
    const float* state_out = (const float*)d_in[1];
    const float* state_cur = (const float*)d_in[2];
    const float* A_vals    = (const float*)d_in[3];
    const int*   A_rows    = (const int*)  d_in[4];
    const int*   A_cols    = (const int*)  d_in[5];
    const float* W_r       = (const float*)d_in[6];
    const float* b_r       = (const float*)d_in[7];
    const float* W_z       = (const float*)d_in[8];
    const float* b_z       = (const float*)d_in[9];
    const float* W_h       = (const float*)d_in[10];
    const float* b_h       = (const float*)d_in[11];
    float* out = (float*)d_out;

    cudaFuncSetAttribute(k_main, cudaFuncAttributeMaxDynamicSharedMemorySize, SMEM_TOTAL);

    k_init<<<(3 * 64 * 192 + 255) / 256, 256>>>(W_r, W_z, W_h);
    k_scatter<<<(SEG * NNZE + 255) / 256, 256>>>(A_vals, A_rows, A_cols);
    k_main<<<BB * NBLK, 256, SMEM_TOTAL>>>(state_in, state_out, state_cur,
                                           b_r, b_z, b_h, out);
}

// round 16
// speedup vs baseline: 1.5031x; 1.0103x over previous
#include <cuda_runtime.h>
#include <cuda_fp16.h>
#include <cstdint>

// ---------------- problem constants ----------------
#define BB   8
#define NT   2
#define NN   2000
#define ENN  4000
#define NNZE 32000
#define LL   8
#define DD   64
#define LD   512
#define SEG  (BB*NT)
#define NPB  8             // nodes per block -> M = 64
#define NBLK (NN/NPB)      // 250
#define KD   192
#define BCAP 64            // bucket capacity; Poisson(16) => P(>64) ~ 1e-20

// A smem: 64 rows x 200 fp16 slots (400 B/row, 192 used).
#define AROW 200
#define A_BYTES (64 * AROW * 2)      // 25600
#define SMEM_TOTAL A_BYTES

// ---------------- device scratch ----------------
__device__ int   g_cnt [SEG * NN];            // zero-init at load; re-zeroed by k_main tail
__device__ int2  g_bkt [(size_t)SEG * NN * BCAP];   // packed {val bits, col}
// W image: [mat(3)][n(64)][k(192)] fp16
__device__ __align__(16) __half g_W16[3 * 64 * 192];

// ---------------- helpers ----------------
__device__ __forceinline__ uint32_t smem_u32(const void* p) {
    uint32_t a;
    asm("{ .reg .u64 t; cvta.to.shared.u64 t, %1; cvt.u32.u64 %0, t; }" : "=r"(a) : "l"(p));
    return a;
}
__device__ __forceinline__ float sigm(float x) { return 1.0f / (1.0f + __expf(-x)); }

#define LDMATRIX_X4(r0, r1, r2, r3, addr) \
    asm volatile("ldmatrix.sync.aligned.m8n8.x4.shared.b16 {%0,%1,%2,%3}, [%4];" \
        : "=r"(r0), "=r"(r1), "=r"(r2), "=r"(r3) : "r"(addr))

#define MMA16816F16(c, a0, a1, a2, a3, b0, b1) \
    asm volatile("mma.sync.aligned.m16n8k16.row.col.f32.f16.f16.f32 " \
        "{%0,%1,%2,%3}, {%4,%5,%6,%7}, {%8,%9}, {%0,%1,%2,%3};" \
        : "+f"((c)[0]), "+f"((c)[1]), "+f"((c)[2]), "+f"((c)[3]) \
        : "r"(a0), "r"(a1), "r"(a2), "r"(a3), "r"(b0), "r"(b1))

// ---------------- scatter + fused W prep ----------------
// g_cnt is zero on entry: static zero-init on first call, re-zeroed by the
// previous k_main on every subsequent (graph-replayed) call.
__global__ void k_scatter(const float* __restrict__ vals,
                          const int*   __restrict__ rows,
                          const int*   __restrict__ cols,
                          const float* __restrict__ Wr,
                          const float* __restrict__ Wz,
                          const float* __restrict__ Wh) {
    int idx = blockIdx.x * blockDim.x + threadIdx.x;
    if (idx < 3 * 64 * 192) {
        int mat = idx / (64 * 192);
        int r   = idx - mat * (64 * 192);
        const float* W = (mat == 0) ? Wr : (mat == 1) ? Wz : Wh;
        g_W16[idx] = __float2half(W[r]);
    }
    if (idx >= SEG * NNZE) return;
    int seg = idx / NNZE;
    int slot = seg * NN + rows[idx];
    int pos = atomicAdd(&g_cnt[slot], 1);
    if (pos < BCAP)
        g_bkt[(size_t)slot * BCAP + pos] = make_int2(__float_as_int(vals[idx]), cols[idx]);
}

// ---------------- main fused kernel ----------------
__global__ void __launch_bounds__(256, 3)
k_main(const float* __restrict__ state_in,
       const float* __restrict__ state_out,
       const float* __restrict__ state_cur,
       const float* __restrict__ b_r,
       const float* __restrict__ b_z,
       const float* __restrict__ b_h,
       float* __restrict__ out) {
    extern __shared__ char smem[];
    __half* As = reinterpret_cast<__half*>(smem);
    const uint32_t sbh = smem_u32(smem);

    const int tid  = threadIdx.x;
    const int w    = tid >> 5;
    const int lane = tid & 31;
    const int b    = blockIdx.x / NBLK;
    const int nb   = (blockIdx.x - b * NBLK) * NPB;

    // ---------- Phase 1: SpMM gather (fp32, pipelined dist-2) ----------
    for (int task = w; task < 16; task += 8) {
        const int node = task >> 1;
        const int type = task & 1;
        const int n    = nb + node;
        const int seg  = b * NT + type;
        const int slot = seg * NN + n;
        const float* S  = (type == 0 ? state_in : state_out) + (size_t)b * ENN * LD;
        const int2*  E  = g_bkt + (size_t)slot * BCAP;
        int rem = g_cnt[slot];
        if (rem > BCAP) rem = BCAP;

        float4 a0 = {0,0,0,0}, a1 = {0,0,0,0}, a2 = {0,0,0,0}, a3 = {0,0,0,0};

        if (rem > 0) {
            int2 e0 = __ldg(&E[0]);
            int2 e1 = __ldg(&E[(rem > 1) ? 1 : 0]);
            const float4* r0p = reinterpret_cast<const float4*>(S + (size_t)e0.y * LD);
            const float4* r1p = reinterpret_cast<const float4*>(S + (size_t)e1.y * LD);
            float4 p00 = __ldg(r0p + lane);
            float4 p01 = __ldg(r0p + 32 + lane);
            float4 p02 = __ldg(r0p + 64 + lane);
            float4 p03 = __ldg(r0p + 96 + lane);
            float4 p10 = __ldg(r1p + lane);
            float4 p11 = __ldg(r1p + 32 + lane);
            float4 p12 = __ldg(r1p + 64 + lane);
            float4 p13 = __ldg(r1p + 96 + lane);

            int i = 0;
            while (i + 2 <= rem) {
                const int i2 = (i + 2 < rem) ? (i + 2) : (rem - 1);
                const int i3 = (i + 3 < rem) ? (i + 3) : (rem - 1);
                int2 f0 = __ldg(&E[i2]);
                int2 f1 = __ldg(&E[i3]);

                const float va = __int_as_float(e0.x);
                const float vb = __int_as_float(e1.x);

                a0.x += va * p00.x; a0.y += va * p00.y; a0.z += va * p00.z; a0.w += va * p00.w;
                a1.x += va * p01.x; a1.y += va * p01.y; a1.z += va * p01.z; a1.w += va * p01.w;
                a2.x += va * p02.x; a2.y += va * p02.y; a2.z += va * p02.z; a2.w += va * p02.w;
                a3.x += va * p03.x; a3.y += va * p03.y; a3.z += va * p03.z; a3.w += va * p03.w;
                a0.x += vb * p10.x; a0.y += vb * p10.y; a0.z += vb * p10.z; a0.w += vb * p10.w;
                a1.x += vb * p11.x; a1.y += vb * p11.y; a1.z += vb * p11.z; a1.w += vb * p11.w;
                a2.x += vb * p12.x; a2.y += vb * p12.y; a2.z += vb * p12.z; a2.w += vb * p12.w;
                a3.x += vb * p13.x; a3.y += vb * p13.y; a3.z += vb * p13.z; a3.w += vb * p13.w;

                const float4* q0p = reinterpret_cast<const float4*>(S + (size_t)f0.y * LD);
                const float4* q1p = reinterpret_cast<const float4*>(S + (size_t)f1.y * LD);
                p00 = __ldg(q0p + lane);
                p01 = __ldg(q0p + 32 + lane);
                p02 = __ldg(q0p + 64 + lane);
                p03 = __ldg(q0p + 96 + lane);
                p10 = __ldg(q1p + lane);
                p11 = __ldg(q1p + 32 + lane);
                p12 = __ldg(q1p + 64 + lane);
                p13 = __ldg(q1p + 96 + lane);

                e0 = f0; e1 = f1;
                i += 2;
            }
            if (i < rem) {
                const float va = __int_as_float(e0.x);
                a0.x += va * p00.x; a0.y += va * p00.y; a0.z += va * p00.z; a0.w += va * p00.w;
                a1.x += va * p01.x; a1.y += va * p01.y; a1.z += va * p01.z; a1.w += va * p01.w;
                a2.x += va * p02.x; a2.y += va * p02.y; a2.z += va * p02.z; a2.w += va * p02.w;
                a3.x += va * p03.x; a3.y += va * p03.y; a3.z += va * p03.z; a3.w += va * p03.w;
            }
        }

        float4 acc[4] = {a0, a1, a2, a3};
#pragma unroll
        for (int j = 0; j < 4; ++j) {
            const int Eidx = j * 32 + lane;
            const int l    = Eidx >> 4;
            const int d4   = (Eidx & 15) * 4;
            const int row  = node * LL + l;
            const int kb   = type * DD + d4;
            float4 vx = acc[j];
            __half2 h01 = __floats2half2_rn(vx.x, vx.y);
            __half2 h23 = __floats2half2_rn(vx.z, vx.w);
            uint2 hw;
            hw.x = *reinterpret_cast<uint32_t*>(&h01);
            hw.y = *reinterpret_cast<uint32_t*>(&h23);
            *reinterpret_cast<uint2*>(&As[row * AROW + kb]) = hw;
        }
    }
    // state_cur: warp w loads node w
    {
        const int n = nb + w;
        const float4* C = reinterpret_cast<const float4*>(state_cur + (size_t)(b * NN + n) * LD);
#pragma unroll
        for (int j = 0; j < 4; ++j) {
            const int Eidx = j * 32 + lane;
            const int l    = Eidx >> 4;
            const int d4   = (Eidx & 15) * 4;
            float4 vx = __ldg(C + Eidx);
            const int row = w * LL + l;
            const int kb  = 128 + d4;
            __half2 h01 = __floats2half2_rn(vx.x, vx.y);
            __half2 h23 = __floats2half2_rn(vx.z, vx.w);
            uint2 hw;
            hw.x = *reinterpret_cast<uint32_t*>(&h01);
            hw.y = *reinterpret_cast<uint32_t*>(&h23);
            *reinterpret_cast<uint2*>(&As[row * AROW + kb]) = hw;
        }
    }
    __syncthreads();   // ALL warps have read their g_cnt slots before this point

    // re-zero this block's 16 g_cnt slots for the next graph replay
    // (safe: after the barrier, no thread in this block reads g_cnt again)
    if (tid < 16) {
        const int node = tid >> 1;
        const int type = tid & 1;
        g_cnt[(b * NT + type) * NN + nb + node] = 0;
    }

    // ---------- Phase 2: fp16 HMMA GEMMs (single term) ----------
    const int n0 = w * 8;
    const int qr = lane >> 2;
    const int qc = (lane & 3) * 2;

    float cr[16], cz[16], ch[16];
#pragma unroll
    for (int i = 0; i < 16; ++i) { cr[i] = 0.0f; cz[i] = 0.0f; ch[i] = 0.0f; }

    const int arow = lane & 15;
    const int koff16 = ((lane >> 4) & 1) * 16;
    const int bnr = (n0 + qr) * 192 + qc;

#pragma unroll
    for (int kt = 0; kt < 8; ++kt) {
        const int k0 = kt * 16;
        const uint32_t br0 = *reinterpret_cast<const uint32_t*>(g_W16 + bnr + k0);
        const uint32_t br1 = *reinterpret_cast<const uint32_t*>(g_W16 + bnr + k0 + 8);
        const uint32_t bz0 = *reinterpret_cast<const uint32_t*>(g_W16 + 64*192 + bnr + k0);
        const uint32_t bz1 = *reinterpret_cast<const uint32_t*>(g_W16 + 64*192 + bnr + k0 + 8);
        const uint32_t bh0 = *reinterpret_cast<const uint32_t*>(g_W16 + 128*192 + bnr + k0);
        const uint32_t bh1 = *reinterpret_cast<const uint32_t*>(g_W16 + 128*192 + bnr + k0 + 8);
#pragma unroll
        for (int i = 0; i < 4; ++i) {
            const uint32_t aoff = (uint32_t)((16 * i + arow) * 400 + k0 * 2 + koff16);
            uint32_t a0, a1, a2, a3;
            LDMATRIX_X4(a0, a1, a2, a3, sbh + aoff);
            MMA16816F16(cr + 4*i, a0, a1, a2, a3, br0, br1);
            MMA16816F16(cz + 4*i, a0, a1, a2, a3, bz0, bz1);
            MMA16816F16(ch + 4*i, a0, a1, a2, a3, bh0, bh1);
        }
    }
#pragma unroll
    for (int kt = 8; kt < 12; ++kt) {
        const int k0 = kt * 16;
        const uint32_t br0 = *reinterpret_cast<const uint32_t*>(g_W16 + bnr + k0);
        const uint32_t br1 = *reinterpret_cast<const uint32_t*>(g_W16 + bnr + k0 + 8);
        const uint32_t bz0 = *reinterpret_cast<const uint32_t*>(g_W16 + 64*192 + bnr + k0);
        const uint32_t bz1 = *reinterpret_cast<const uint32_t*>(g_W16 + 64*192 + bnr + k0 + 8);
#pragma unroll
        for (int i = 0; i < 4; ++i) {
            const uint32_t aoff = (uint32_t)((16 * i + arow) * 400 + k0 * 2 + koff16);
            uint32_t a0, a1, a2, a3;
            LDMATRIX_X4(a0, a1, a2, a3, sbh + aoff);
            MMA16816F16(cr + 4*i, a0, a1, a2, a3, br0, br1);
            MMA16816F16(cz + 4*i, a0, a1, a2, a3, bz0, bz1);
        }
    }
    __syncthreads();

    // ---------- Epilogue 1: r, z; write rc = r*cur over cur columns ----------
    float curv[16], zreg[16];
#pragma unroll
    for (int i = 0; i < 4; ++i) {
#pragma unroll
        for (int rr = 0; rr < 2; ++rr) {
            const int m = 16 * i + qr + 8 * rr;
#pragma unroll
            for (int cc = 0; cc < 2; ++cc) {
                const int o   = n0 + qc + cc;
                const int idx = i * 4 + rr * 2 + cc;
                const int e   = m * AROW + 128 + o;
                const float cur = __half2float(As[e]);
                curv[idx] = cur;
                const float rv = sigm(cr[idx] + __ldg(&b_r[o]));
                zreg[idx] = sigm(cz[idx] + __ldg(&b_z[o]));
                As[e] = __float2half(rv * cur);
            }
        }
    }
    __syncthreads();

    // ---------- Phase 3: finish h with rc columns ----------
#pragma unroll
    for (int kt = 8; kt < 12; ++kt) {
        const int k0 = kt * 16;
        const uint32_t bh0 = *reinterpret_cast<const uint32_t*>(g_W16 + 128*192 + bnr + k0);
        const uint32_t bh1 = *reinterpret_cast<const uint32_t*>(g_W16 + 128*192 + bnr + k0 + 8);
#pragma unroll
        for (int i = 0; i < 4; ++i) {
            const uint32_t aoff = (uint32_t)((16 * i + arow) * 400 + k0 * 2 + koff16);
            uint32_t a0, a1, a2, a3;
            LDMATRIX_X4(a0, a1, a2, a3, sbh + aoff);
            MMA16816F16(ch + 4*i, a0, a1, a2, a3, bh0, bh1);
        }
    }

    // ---------- Epilogue 2: GRU combine + store ----------
#pragma unroll
    for (int i = 0; i < 4; ++i) {
#pragma unroll
        for (int rr = 0; rr < 2; ++rr) {
            const int m    = 16 * i + qr + 8 * rr;
            const int node = m >> 3;
            const int l    = m & 7;
            const size_t grow = ((size_t)(b * NN + nb + node) * LL + l);
            float2 v;
#pragma unroll
            for (int cc = 0; cc < 2; ++cc) {
                const int o   = n0 + qc + cc;
                const int idx = i * 4 + rr * 2 + cc;
                const float h = tanhf(ch[idx] + __ldg(&b_h[o]));
                const float z = zreg[idx];
                const float r2 = (1.0f - z) * curv[idx] + z * h;
                if (cc == 0) v.x = r2; else v.y = r2;
            }
            *reinterpret_cast<float2*>(out + grow * DD + n0 + qc) = v;
        }
    }
}

// ---------------- launch ----------------
extern "C" void kernel_launch(void* const* d_in, const int* in_sizes, int n_in,
                              void* d_out, int out_size) {
    (void)in_sizes; (void)n_in; (void)out_size;
    const float* state_in  = (const float*)d_in[0];
    const float* state_out = (const float*)d_in[1];
    const float* state_cur = (const float*)d_in[2];
    const float* A_vals    = (const float*)d_in[3];
    const int*   A_rows    = (const int*)  d_in[4];
    const int*   A_cols    = (const int*)  d_in[5];
    const float* W_r       = (const float*)d_in[6];
    const float* b_r       = (const float*)d_in[7];
    const float* W_z       = (const float*)d_in[8];
    const float* b_z       = (const float*)d_in[9];
    const float* W_h       = (const float*)d_in[10];
    const float* b_h       = (const float*)d_in[11];
    float* out = (float*)d_out;

    cudaFuncSetAttribute(k_main, cudaFuncAttributeMaxDynamicSharedMemorySize, SMEM_TOTAL);

    k_scatter<<<(SEG * NNZE + 255) / 256, 256>>>(A_vals, A_rows, A_cols, W_r, W_z, W_h);
    k_main<<<BB * NBLK, 256, SMEM_TOTAL>>>(state_in, state_out, state_cur,
                                           b_r, b_z, b_h, out);
}